// round 3
// baseline (speedup 1.0000x reference)
#include <cuda_runtime.h>
#include <cstdint>

#define D 1024
#define WARPS 4          // warps per block
#define RPW 2            // rows per warp (packed into u64 smem slots)

typedef unsigned long long u64;

// ---------- packed f32x2 helpers (sm_103a) ----------
__device__ __forceinline__ u64 pack2(float a, float b) {
    u64 r; asm("mov.b64 %0, {%1, %2};" : "=l"(r) : "f"(a), "f"(b)); return r;
}
__device__ __forceinline__ void unpack2(u64 v, float& a, float& b) {
    asm("mov.b64 {%0, %1}, %2;" : "=f"(a), "=f"(b) : "l"(v));
}
__device__ __forceinline__ u64 add2(u64 a, u64 b) {
    u64 r; asm("add.rn.f32x2 %0, %1, %2;" : "=l"(r) : "l"(a), "l"(b)); return r;
}
__device__ __forceinline__ u64 mul2(u64 a, u64 b) {
    u64 r; asm("mul.rn.f32x2 %0, %1, %2;" : "=l"(r) : "l"(a), "l"(b)); return r;
}
__device__ __forceinline__ u64 fma2(u64 a, u64 b, u64 c) {
    u64 r; asm("fma.rn.f32x2 %0, %1, %2, %3;" : "=l"(r) : "l"(a), "l"(b), "l"(c)); return r;
}

// In-register FWHT over the 32-element register axis (pack k = axis values 2k,2k+1)
__device__ __forceinline__ void fwht32(u64 v[16]) {
    const u64 NEG1 = 0xBF800000BF800000ULL;  // (-1.f, -1.f)
    #pragma unroll
    for (int k = 0; k < 16; k++) {
        float a, b; unpack2(v[k], a, b);
        v[k] = pack2(a + b, a - b);
    }
    #pragma unroll
    for (int h = 1; h <= 8; h <<= 1) {
        #pragma unroll
        for (int k = 0; k < 16; k++) {
            if (!(k & h)) {
                u64 A = v[k], B = v[k + h];
                v[k]     = add2(A, B);
                v[k + h] = fma2(B, NEG1, A);
            }
        }
    }
}

// u64-slot exchange layout for a logical 32x32 grid (m = row, c = col):
//   phys(m, c) = m*32 + (((c>>1) ^ m) & 15)*2 + (c & 1)      (u64 index)
// Properties:
//  * scalar STS.64 row-write (fixed m, c = lane): all 32 slots distinct, and within
//    each 16-lane/128B phase the 8B slots are distinct -> conflict-free
//  * LDS.128 row-read (m = lane, c = {2c2, 2c2+1}): adjacent u64s, 16B aligned;
//    per 8-lane phase the float4 columns (c2 ^ lane) & 7 are distinct -> conflict-free
__device__ __forceinline__ int physmc(int m, int c) {
    return m * 32 + (((c >> 1) ^ m) & 15) * 2 + (c & 1);
}

// Precomputed tables (allocation-free scratch)
__device__ int   g_Qt[D];   // scatter targets: Qt[(e&31)*32 + (e>>5)] = phys slot of t with P[t]=e
__device__ float g_St[D];   // St[(t&31)*32 + (t>>5)] = S[t]/32

__global__ void fastfood_prep(const int* __restrict__ P, const float* __restrict__ S) {
    int i = blockIdx.x * blockDim.x + threadIdx.x;   // i = t
    if (i < D) {
        int e = P[i];
        // slot for t = i holds value HBx[P[t]]; slot convention: (m = t>>5, c = t&31)
        g_Qt[(e & 31) * 32 + (e >> 5)] = physmc(i >> 5, i & 31);
        g_St[(i & 31) * 32 + (i >> 5)] = S[i] * 0.03125f;  // 1/sqrt(1024), SCALE=1
    }
}

__global__ __launch_bounds__(WARPS * 32, 4)
void fastfood_kernel(const float* __restrict__ x, const float* __restrict__ B,
                     const float* __restrict__ G, float* __restrict__ out, int nrows) {
    __shared__ u64 buf[WARPS][D];      // 32 KB/block: one u64 slot per element, 2 rows packed
    const int warp = threadIdx.x >> 5;
    const int lane = threadIdx.x & 31;
    const int pair = blockIdx.x * WARPS + warp;
    if (pair * RPW >= nrows) return;

    u64* sb = buf[warp];
    const float4* sb4 = reinterpret_cast<const float4*>(sb);

    u64 va[16], vb[16];

    // ---- load x*B (contiguous ownership e = lane*32 + k), all float4 ----
    const float4* Bv = reinterpret_cast<const float4*>(B) + lane * 8;
    const float4* xa = reinterpret_cast<const float4*>(x) + (size_t)(pair * RPW) * (D / 4) + lane * 8;
    const float4* xb = xa + (D / 4);
    #pragma unroll
    for (int c4 = 0; c4 < 8; c4++) {
        float4 bb = Bv[c4];
        float4 fa = xa[c4];
        float4 fb = xb[c4];
        u64 b01 = pack2(bb.x, bb.y), b23 = pack2(bb.z, bb.w);
        va[2*c4]   = mul2(pack2(fa.x, fa.y), b01);
        va[2*c4+1] = mul2(pack2(fa.z, fa.w), b23);
        vb[2*c4]   = mul2(pack2(fb.x, fb.y), b01);
        vb[2*c4+1] = mul2(pack2(fb.z, fb.w), b23);
    }

    // ---- WHT #1, low 5 bits of e (register axis) ----
    fwht32(va); fwht32(vb);

    // ---- exchange 1 (transpose): element k of lane -> slot (m=k, c=lane) ----
    #pragma unroll
    for (int k = 0; k < 16; k++) {
        float a0, a1, b0, b1;
        unpack2(va[k], a0, a1);
        unpack2(vb[k], b0, b1);
        sb[physmc(2*k,     lane)] = pack2(a0, b0);
        sb[physmc(2*k + 1, lane)] = pack2(a1, b1);
    }
    __syncwarp();
    // read row m=lane: reg c2 -> elements e = {2c2, 2c2+1}*32 + lane
    #pragma unroll
    for (int c2 = 0; c2 < 16; c2++) {
        float4 f = sb4[lane * 16 + ((c2 ^ lane) & 15)];
        va[c2] = pack2(f.x, f.z);
        vb[c2] = pack2(f.y, f.w);
    }

    // ---- WHT #1, high 5 bits (thread owns e = m*32 + lane, m = reg) ----
    fwht32(va); fwht32(vb);
    __syncwarp();   // exchange-1 reads complete before scatter overwrites

    // ---- exchange 2 (permutation): scatter HBx[e] to slot of t = Pinv[e] ----
    const int4* Q4 = reinterpret_cast<const int4*>(g_Qt) + lane * 8;
    #pragma unroll
    for (int c4 = 0; c4 < 8; c4++) {
        int4 q = Q4[c4];      // targets for m = 4c4 .. 4c4+3
        float a0, a1, a2, a3, b0, b1, b2, b3;
        unpack2(va[2*c4],   a0, a1);
        unpack2(va[2*c4+1], a2, a3);
        unpack2(vb[2*c4],   b0, b1);
        unpack2(vb[2*c4+1], b2, b3);
        sb[q.x] = pack2(a0, b0);
        sb[q.y] = pack2(a1, b1);
        sb[q.z] = pack2(a2, b2);
        sb[q.w] = pack2(a3, b3);
    }
    __syncwarp();

    // ---- gather contiguous t (row m=lane) and multiply G (natural order) ----
    const float4* Gv = reinterpret_cast<const float4*>(G) + lane * 8;
    #pragma unroll
    for (int c4 = 0; c4 < 8; c4++) {
        float4 f0 = sb4[lane * 16 + (((2*c4)     ^ lane) & 15)];
        float4 f1 = sb4[lane * 16 + (((2*c4 + 1) ^ lane) & 15)];
        float4 g  = Gv[c4];
        u64 g01 = pack2(g.x, g.y), g23 = pack2(g.z, g.w);
        va[2*c4]   = mul2(pack2(f0.x, f0.z), g01);
        vb[2*c4]   = mul2(pack2(f0.y, f0.w), g01);
        va[2*c4+1] = mul2(pack2(f1.x, f1.z), g23);
        vb[2*c4+1] = mul2(pack2(f1.y, f1.w), g23);
    }

    // ---- WHT #2, low 5 bits of t ----
    fwht32(va); fwht32(vb);
    __syncwarp();

    // ---- exchange 3 (transpose) ----
    #pragma unroll
    for (int k = 0; k < 16; k++) {
        float a0, a1, b0, b1;
        unpack2(va[k], a0, a1);
        unpack2(vb[k], b0, b1);
        sb[physmc(2*k,     lane)] = pack2(a0, b0);
        sb[physmc(2*k + 1, lane)] = pack2(a1, b1);
    }
    __syncwarp();
    #pragma unroll
    for (int c2 = 0; c2 < 16; c2++) {
        float4 f = sb4[lane * 16 + ((c2 ^ lane) & 15)];
        va[c2] = pack2(f.x, f.z);
        vb[c2] = pack2(f.y, f.w);
    }

    // ---- WHT #2, high 5 bits (thread owns t = m*32 + lane) ----
    fwht32(va); fwht32(vb);

    // ---- scale by S/32 (pre-transposed table) and store coalesced ----
    const float4* Sv = reinterpret_cast<const float4*>(g_St) + lane * 8;
    float* oa = out + (size_t)(pair * RPW) * D;
    float* ob = oa + D;
    #pragma unroll
    for (int c4 = 0; c4 < 8; c4++) {
        float4 s = Sv[c4];
        u64 s01 = pack2(s.x, s.y), s23 = pack2(s.z, s.w);
        u64 ra0 = mul2(va[2*c4],   s01);
        u64 ra1 = mul2(va[2*c4+1], s23);
        u64 rb0 = mul2(vb[2*c4],   s01);
        u64 rb1 = mul2(vb[2*c4+1], s23);
        float p0, p1, p2, p3;
        unpack2(ra0, p0, p1); unpack2(ra1, p2, p3);
        oa[(4*c4+0)*32 + lane] = p0;
        oa[(4*c4+1)*32 + lane] = p1;
        oa[(4*c4+2)*32 + lane] = p2;
        oa[(4*c4+3)*32 + lane] = p3;
        unpack2(rb0, p0, p1); unpack2(rb1, p2, p3);
        ob[(4*c4+0)*32 + lane] = p0;
        ob[(4*c4+1)*32 + lane] = p1;
        ob[(4*c4+2)*32 + lane] = p2;
        ob[(4*c4+3)*32 + lane] = p3;
    }
}

extern "C" void kernel_launch(void* const* d_in, const int* in_sizes, int n_in,
                              void* d_out, int out_size) {
    const float* x = (const float*)d_in[0];
    const float* B = (const float*)d_in[1];
    const float* G = (const float*)d_in[2];
    const float* S = (const float*)d_in[3];
    const int*   P = (const int*)d_in[4];
    float* out = (float*)d_out;

    const int nrows = in_sizes[0] / D;

    fastfood_prep<<<(D + 255) / 256, 256>>>(P, S);

    const int rows_per_block = WARPS * RPW;
    const int blocks = (nrows + rows_per_block - 1) / rows_per_block;
    fastfood_kernel<<<blocks, WARPS * 32>>>(x, B, G, out, nrows);
}